// round 1
// baseline (speedup 1.0000x reference)
#include <cuda_runtime.h>
#include <cuda_fp16.h>
#include <stdint.h>

#define TT      365
#define BATCH   4096
#define HID     256
#define INND    32
#define KDIM    288     // 256 (h) + 32 (x)
#define NGATE   1024
#define MTILE   32      // batch rows per CTA
#define NCTA    128
#define NTHREADS 256
#define KSTEPS  18      // 288/16
#define NTILES  128     // 1024/8
#define LDA     296     // A smem row stride (halfs)
#define LDGATE  1032    // gates smem row stride (floats)

#define SMEM_A_BYTES  (MTILE * LDA * 2)          // 18944
#define SMEM_G_BYTES  (MTILE * LDGATE * 4)       // 132096
#define SMEM_BYTES    (SMEM_A_BYTES + SMEM_G_BYTES)

// Pre-swizzled fp16 weights in exact mma.m16n8k16 B-fragment order.
// Index: ((kstep*128 + ntile)*32 + lane) -> uint2 {B[k,n]B[k+1,n], B[k+8,n]B[k+9,n]}
__device__ uint2 g_WcSwz[KSTEPS * NTILES * 32];

// ---------------------------------------------------------------------------
// Prep: gather w_hh (K=0..255) and w_ih (K=256..287) into fragment order, fp16
// ---------------------------------------------------------------------------
__global__ void lstm_prep_kernel(const float* __restrict__ w_ih,
                                 const float* __restrict__ w_hh) {
    int g = blockIdx.x * blockDim.x + threadIdx.x;
    if (g >= KSTEPS * NTILES * 32) return;
    int lane  = g & 31;
    int ntile = (g >> 5) & 127;
    int kstep = g >> 12;           // g / 4096
    int n0 = ntile * 8 + (lane >> 2);      // gate row (0..1023)
    int kb = kstep * 16 + 2 * (lane & 3);  // k offset

    float v[4];
    int koffs[4] = {kb, kb + 1, kb + 8, kb + 9};
#pragma unroll
    for (int u = 0; u < 4; u++) {
        int k = koffs[u];
        v[u] = (k < 256) ? w_hh[n0 * 256 + k] : w_ih[n0 * 32 + (k - 256)];
    }
    unsigned x = ((unsigned)__half_as_ushort(__float2half(v[1])) << 16)
               |  (unsigned)__half_as_ushort(__float2half(v[0]));
    unsigned y = ((unsigned)__half_as_ushort(__float2half(v[3])) << 16)
               |  (unsigned)__half_as_ushort(__float2half(v[2]));
    uint2 val; val.x = x; val.y = y;
    g_WcSwz[g] = val;
}

// ---------------------------------------------------------------------------
// Device helpers
// ---------------------------------------------------------------------------
__device__ __forceinline__ unsigned smem_u32(const void* p) {
    return (unsigned)__cvta_generic_to_shared(p);
}

__device__ __forceinline__ void ldmatrix_x4(unsigned addr, unsigned& r0,
                                            unsigned& r1, unsigned& r2, unsigned& r3) {
    asm volatile("ldmatrix.sync.aligned.m8n8.x4.shared.b16 {%0,%1,%2,%3}, [%4];\n"
                 : "=r"(r0), "=r"(r1), "=r"(r2), "=r"(r3)
                 : "r"(addr));
}

__device__ __forceinline__ void mma16816(float* c, unsigned a0, unsigned a1,
                                         unsigned a2, unsigned a3,
                                         unsigned b0, unsigned b1) {
    asm volatile(
        "mma.sync.aligned.m16n8k16.row.col.f32.f16.f16.f32 "
        "{%0,%1,%2,%3}, {%4,%5,%6,%7}, {%8,%9}, {%0,%1,%2,%3};\n"
        : "+f"(c[0]), "+f"(c[1]), "+f"(c[2]), "+f"(c[3])
        : "r"(a0), "r"(a1), "r"(a2), "r"(a3), "r"(b0), "r"(b1));
}

__device__ __forceinline__ float sigf(float x) {
    // 1/(1+exp(-x)) via MUFU.EX2 + MUFU.RCP (~1e-7 rel err)
    return __fdividef(1.f, 1.f + __expf(-x));
}

__device__ __forceinline__ float tanh_safe(float x) {
    // overflow-safe: tanh(x) = sign(x) * (1-e)/(1+e), e = exp(-2|x|) in (0,1]
    float ax = fabsf(x);
    float e  = __expf(-2.f * ax);
    float r  = __fdividef(1.f - e, 1.f + e);
    return copysignf(r, x);
}

// ---------------------------------------------------------------------------
// Persistent LSTM kernel: one CTA owns 32 batch rows for all 365 steps
// ---------------------------------------------------------------------------
__global__ void __launch_bounds__(NTHREADS, 1)
lstm_main_kernel(const float* __restrict__ xd,
                 const float* __restrict__ b,
                 const float* __restrict__ w_out,
                 const float* __restrict__ b_out,
                 float* __restrict__ out) {
    extern __shared__ char smem[];
    __half* A     = (__half*)smem;                    // [32][LDA]  = [h | x] fp16
    float*  gates = (float*)(smem + SMEM_A_BYTES);    // [32][LDGATE]

    const int tid  = threadIdx.x;
    const int lane = tid & 31;
    const int warp = tid >> 5;
    const int rowbase = blockIdx.x * MTILE;

    // zero h-part of A (cols 0..255)
    for (int idx = tid; idx < MTILE * 128; idx += NTHREADS) {
        int r = idx >> 7, c2 = idx & 127;
        ((__half2*)(A + r * LDA))[c2] = __half2half2(__float2half(0.f));
    }

    // per-thread biases (thread tid owns hidden column j = tid)
    const float bi = b[tid];
    const float bf = b[tid + 256];
    const float bg = b[tid + 512];
    const float bo = b[tid + 768];

    float c_reg[MTILE];
#pragma unroll
    for (int k = 0; k < MTILE; k++) c_reg[k] = 0.f;

    // ldmatrix per-thread address components
    const int lrow = lane & 7;
    const int lsel = lane >> 3;
    const int aRowOff = lrow + ((lsel & 1) << 3);
    const int aColOff = (lsel >> 1) << 3;

    // accumulator write coords
    const int cRow = lane >> 2;
    const int cCol = (lane & 3) * 2;

    for (int t = 0; t < TT; t++) {
        // ---- phase 1: stage x_t (fp32 -> fp16) into A[:, 256:288] ----
#pragma unroll
        for (int u = 0; u < 4; u++) {
            int idx = tid + u * NTHREADS;       // 0..1023
            int r = idx >> 5, i = idx & 31;
            float xv = xd[(rowbase + r) * (TT * INND) + t * INND + i];
            A[r * LDA + 256 + i] = __float2half(xv);
        }
        __syncthreads();

        // ---- phase 2: gates[32x1024] = [h|x] @ Wc^T  (fp16 mma, fp32 accum) ----
        float acc[2][16][4];
#pragma unroll
        for (int mt = 0; mt < 2; mt++)
#pragma unroll
            for (int nt = 0; nt < 16; nt++)
#pragma unroll
                for (int u = 0; u < 4; u++) acc[mt][nt][u] = 0.f;

#pragma unroll
        for (int ks = 0; ks < KSTEPS; ks++) {
            const int k0 = ks * 16;
            unsigned a[2][4];
#pragma unroll
            for (int mt = 0; mt < 2; mt++) {
                const __half* p = A + (mt * 16 + aRowOff) * LDA + k0 + aColOff;
                ldmatrix_x4(smem_u32(p), a[mt][0], a[mt][1], a[mt][2], a[mt][3]);
            }
            const uint2* wp = g_WcSwz + (ks * NTILES + warp * 16) * 32 + lane;
#pragma unroll
            for (int nt = 0; nt < 16; nt++) {
                uint2 bb = __ldcg(wp + nt * 32);
                mma16816(acc[0][nt], a[0][0], a[0][1], a[0][2], a[0][3], bb.x, bb.y);
                mma16816(acc[1][nt], a[1][0], a[1][1], a[1][2], a[1][3], bb.x, bb.y);
            }
        }

        // write accumulators to gates smem
#pragma unroll
        for (int mt = 0; mt < 2; mt++) {
#pragma unroll
            for (int nt = 0; nt < 16; nt++) {
                int ncol = warp * 128 + nt * 8 + cCol;
                *(float2*)&gates[(mt * 16 + cRow) * LDGATE + ncol] =
                    make_float2(acc[mt][nt][0], acc[mt][nt][1]);
                *(float2*)&gates[(mt * 16 + cRow + 8) * LDGATE + ncol] =
                    make_float2(acc[mt][nt][2], acc[mt][nt][3]);
            }
        }
        __syncthreads();

        // ---- phase 3: elementwise cell update; thread owns column j=tid ----
#pragma unroll
        for (int k = 0; k < MTILE; k++) {
            const float* gr = gates + k * LDGATE;
            float pi = gr[tid]       + bi;
            float pf = gr[tid + 256] + bf;
            float pg = gr[tid + 512] + bg;
            float po = gr[tid + 768] + bo;
            float ig = sigf(pi);
            float fg = sigf(pf);
            float gg = tanh_safe(pg);
            float og = sigf(po);
            float c  = fg * c_reg[k] + ig * gg;
            c_reg[k] = c;
            float h  = og * tanh_safe(c);
            A[k * LDA + tid] = __float2half(h);
        }
        __syncthreads();
    }

    // ---- output: out[b] = relu(dot(h_T[b,:], w_out) + b_out) ----
    float wj = w_out[tid];
#pragma unroll
    for (int k = 0; k < MTILE; k++)
        gates[k * LDGATE + tid] = __half2float(A[k * LDA + tid]) * wj;
    __syncthreads();

    float bo0 = b_out[0];
#pragma unroll
    for (int rr = 0; rr < 4; rr++) {
        int k = warp * 4 + rr;
        float s = 0.f;
#pragma unroll
        for (int u = 0; u < 8; u++) s += gates[k * LDGATE + lane + u * 32];
#pragma unroll
        for (int off = 16; off; off >>= 1) s += __shfl_xor_sync(0xffffffffu, s, off);
        if (lane == 0) out[rowbase + k] = fmaxf(s + bo0, 0.f);
    }
}

// ---------------------------------------------------------------------------
extern "C" void kernel_launch(void* const* d_in, const int* in_sizes, int n_in,
                              void* d_out, int out_size) {
    const float* xd    = (const float*)d_in[0];
    const float* w_ih  = (const float*)d_in[1];
    const float* w_hh  = (const float*)d_in[2];
    const float* b     = (const float*)d_in[3];
    const float* w_out = (const float*)d_in[4];
    const float* b_out = (const float*)d_in[5];
    float* out = (float*)d_out;

    cudaFuncSetAttribute(lstm_main_kernel,
                         cudaFuncAttributeMaxDynamicSharedMemorySize, SMEM_BYTES);

    lstm_prep_kernel<<<288, 256>>>(w_ih, w_hh);
    lstm_main_kernel<<<NCTA, NTHREADS, SMEM_BYTES>>>(xd, b, w_out, b_out, out);
}